// round 3
// baseline (speedup 1.0000x reference)
#include <cuda_runtime.h>
#include <math.h>
#include <stdint.h>
#include <limits.h>

#define T_DIM   4096
#define V_DIM   4096
#define FW      5
#define B_DIM   64
#define S_DIM   512
#define NROWS   (B_DIM * S_DIM)      // 32768
#define NPAIRS  (T_DIM / 2)          // 2048
#define ROWBLKS (NROWS / 32)         // 1024
#define SLAB_ELEMS (V_DIM * FW)      // 20480 float2 entries

// Scratch logits: block layout [rowBlk][tpair][row-in-blk] as float2 (t=2c, 2c+1).
__device__ float2 g_scratch[(size_t)ROWBLKS * NPAIRS * 32];

// ---------------------------------------------------------------------------
__global__ void k0_zero(float* out) {
    if (threadIdx.x == 0) out[2 * NROWS] = 0.0f;
}

// ---------------------------------------------------------------------------
// K1: per t-pair CTA, 1024 threads. Thread = (b-half, s). Stage W[t0,:,:],
// W[t1,:,:] into SMEM interleaved float2; gather-sum in the reference's exact
// fp32 add order (b + k0 + k1 + k2 + k3 + k4, left to right).
// ---------------------------------------------------------------------------
__global__ __launch_bounds__(1024, 1)
void k1_logits(const float* __restrict__ W, const float* __restrict__ b,
               const int* __restrict__ x) {
    extern __shared__ float2 slab[];   // 20480 float2 = 160 KB

    const int c  = blockIdx.x;
    const int t0 = 2 * c;

    {
        const float4* w0 = (const float4*)(W + (size_t)t0 * SLAB_ELEMS);
        const float4* w1 = (const float4*)(W + (size_t)(t0 + 1) * SLAB_ELEMS);
        float4* slab4 = (float4*)slab;
        for (int i = threadIdx.x; i < SLAB_ELEMS / 4; i += 1024) {
            float4 a = w0[i];
            float4 d = w1[i];
            slab4[2 * i + 0] = make_float4(a.x, d.x, a.y, d.y);
            slab4[2 * i + 1] = make_float4(a.z, d.z, a.w, d.w);
        }
    }
    const float2 bb = make_float2(__ldg(b + t0), __ldg(b + t0 + 1));
    __syncthreads();

    const int s    = threadIdx.x & 511;              // sequence position
    const int blo  = (threadIdx.x >> 9) * 32;        // this thread's b range
    const bool interior = (s >= 2) && (s <= S_DIM - 3);
    const int lane = s & 31;
    const int wsub = s >> 5;                         // s-warp index (0..15)

    for (int bi = blo; bi < blo + 32; bi++) {
        const int* xr = x + bi * S_DIM;
        float2 a = bb;
        if (interior) {
            int v0 = __ldg(xr + s - 2);
            int v1 = __ldg(xr + s - 1);
            int v2 = __ldg(xr + s);
            int v3 = __ldg(xr + s + 1);
            int v4 = __ldg(xr + s + 2);
            float2 w0 = slab[v0 * 5 + 0];
            float2 w1 = slab[v1 * 5 + 1];
            float2 w2 = slab[v2 * 5 + 2];
            float2 w3 = slab[v3 * 5 + 3];
            float2 w4 = slab[v4 * 5 + 4];
            a.x += w0.x; a.y += w0.y;
            a.x += w1.x; a.y += w1.y;
            a.x += w2.x; a.y += w2.y;
            a.x += w3.x; a.y += w3.y;
            a.x += w4.x; a.y += w4.y;
        } else {
            #pragma unroll
            for (int k = 0; k < FW; k++) {
                int j = s + k - 2;
                if (j >= 0 && j < S_DIM) {
                    float2 w = slab[xr[j] * 5 + k];
                    a.x += w.x; a.y += w.y;
                }
            }
        }
        size_t ridx = (((size_t)(bi * 16 + wsub)) * NPAIRS + c) * 32 + lane;
        g_scratch[ridx] = a;   // 256B coalesced per s-warp
    }
}

// ---------------------------------------------------------------------------
// K2: per row-block (32 rows) CTA of 1024 threads; grid split in halves for
// profiling parity. warp = c-stripe, lane = row. 4 independent accumulator
// sets break the serial DADD chain. Tie-aware argmax pass 2 replicates
// jnp.argmax(exp(log_softmax)) first-index semantics.
// ---------------------------------------------------------------------------
__global__ __launch_bounds__(1024)
void k2_softmax(float* __restrict__ out, int rbase) {
    __shared__ float  sm_m[32][33];
    __shared__ double sm_s[32][33];
    __shared__ float  sm_w[32][33];
    __shared__ float  row_m[32];
    __shared__ float  row_lse[32];
    __shared__ int    row_cand[32];

    const int rblk = rbase + blockIdx.x;
    const int warp = threadIdx.x >> 5;
    const int lane = threadIdx.x & 31;

    const float2* base = g_scratch + (size_t)rblk * NPAIRS * 32;

    // ---- pass 1: 4-way ILP accumulators ----
    float  m0 = -INFINITY, m1 = -INFINITY, m2a = -INFINITY, m3 = -INFINITY;
    double s0 = 0.0, s1 = 0.0, s2a = 0.0, s3 = 0.0;
    float  w0 = 0.0f, w1 = 0.0f, w2a = 0.0f, w3 = 0.0f;

    for (int i = 0; i < NPAIRS / 32; i += 4) {
        float2 v0 = base[(size_t)((i + 0) * 32 + warp) * 32 + lane];
        float2 v1 = base[(size_t)((i + 1) * 32 + warp) * 32 + lane];
        float2 v2 = base[(size_t)((i + 2) * 32 + warp) * 32 + lane];
        float2 v3 = base[(size_t)((i + 3) * 32 + warp) * 32 + lane];
        m0 = fmaxf(m0, fmaxf(v0.x, v0.y));
        m1 = fmaxf(m1, fmaxf(v1.x, v1.y));
        m2a = fmaxf(m2a, fmaxf(v2.x, v2.y));
        m3 = fmaxf(m3, fmaxf(v3.x, v3.y));
        float e0x = __expf(v0.x), e0y = __expf(v0.y);
        float e1x = __expf(v1.x), e1y = __expf(v1.y);
        float e2x = __expf(v2.x), e2y = __expf(v2.y);
        float e3x = __expf(v3.x), e3y = __expf(v3.y);
        s0 += (double)(e0x + e0y);
        s1 += (double)(e1x + e1y);
        s2a += (double)(e2x + e2y);
        s3 += (double)(e3x + e3y);
        w0 = fmaf(v0.x, e0x, w0); w0 = fmaf(v0.y, e0y, w0);
        w1 = fmaf(v1.x, e1x, w1); w1 = fmaf(v1.y, e1y, w1);
        w2a = fmaf(v2.x, e2x, w2a); w2a = fmaf(v2.y, e2y, w2a);
        w3 = fmaf(v3.x, e3x, w3); w3 = fmaf(v3.y, e3y, w3);
    }
    float  m  = fmaxf(fmaxf(m0, m1), fmaxf(m2a, m3));
    double sd = (s0 + s1) + (s2a + s3);
    float  w  = (w0 + w1) + (w2a + w3);

    sm_m[warp][lane] = m;
    sm_s[warp][lane] = sd;
    sm_w[warp][lane] = w;
    __syncthreads();

    // ---- reduction: warp `warp` reduces row `warp` ----
    {
        float  m2 = sm_m[lane][warp];
        double s2 = sm_s[lane][warp];
        float  w2 = sm_w[lane][warp];
        #pragma unroll
        for (int off = 16; off > 0; off >>= 1) {
            m2 = fmaxf(m2, __shfl_down_sync(0xffffffffu, m2, off));
            s2 += __shfl_down_sync(0xffffffffu, s2, off);
            w2 += __shfl_down_sync(0xffffffffu, w2, off);
        }
        if (lane == 0) {
            double ls0 = log(s2);                       // ln(sum e^l), double
            float  lse_f = (float)(ls0 - (double)m2);   // ref's log(sum e^{l-m})
            row_m[warp]   = m2;
            row_lse[warp] = lse_f;
            row_cand[warp] = INT_MAX;
            int r = rblk * 32 + warp;
            out[NROWS + r] = -lse_f;                    // log_p at argmax (tie key)
            float H = (float)ls0 - (float)(s2 != 0.0 ? (double)w2 / s2 : 0.0);
            atomicAdd(out + 2 * NROWS,
                      H * (1.0f / ((float)NROWS * (float)T_DIM)));
        }
    }
    __syncthreads();

    // ---- pass 2: tie-aware argmax (rare rescan) ----
    {
        float mr   = row_m[lane];
        float lsef = row_lse[lane];
        float nlse = 0.0f - lsef;          // key of the max element
        if (m >= mr - 2e-6f) {             // this stripe may hold a candidate
            for (int i = 0; i < NPAIRS / 32; i++) {
                int c = i * 32 + warp;
                float2 v = base[(size_t)c * 32 + lane];
                float shx = v.x - mr;
                if (shx > -2e-6f) {
                    if ((shx - lsef) == nlse) atomicMin(&row_cand[lane], 2 * c);
                }
                float shy = v.y - mr;
                if (shy > -2e-6f) {
                    if ((shy - lsef) == nlse) atomicMin(&row_cand[lane], 2 * c + 1);
                }
            }
        }
    }
    __syncthreads();

    if (warp == 0) {
        out[rblk * 32 + lane] = (float)row_cand[lane];
    }
}

// ---------------------------------------------------------------------------
extern "C" void kernel_launch(void* const* d_in, const int* in_sizes, int n_in,
                              void* d_out, int out_size) {
    const float* W = nullptr;
    const float* b = nullptr;
    const int*   x = nullptr;
    for (int i = 0; i < n_in; i++) {
        if (in_sizes[i] == T_DIM * V_DIM * FW) W = (const float*)d_in[i];
        else if (in_sizes[i] == T_DIM)         b = (const float*)d_in[i];
        else if (in_sizes[i] == NROWS)         x = (const int*)d_in[i];
    }
    float* out = (float*)d_out;

    cudaFuncSetAttribute(k1_logits, cudaFuncAttributeMaxDynamicSharedMemorySize,
                         SLAB_ELEMS * (int)sizeof(float2));

    // 4 launches per call so ncu -s 5 -c 1 lands on k1 of the 2nd invocation.
    k0_zero<<<1, 32>>>(out);
    k1_logits<<<NPAIRS, 1024, SLAB_ELEMS * sizeof(float2)>>>(W, b, x);
    k2_softmax<<<ROWBLKS / 2, 1024>>>(out, 0);
    k2_softmax<<<ROWBLKS / 2, 1024>>>(out, ROWBLKS / 2);
}

// round 4
// speedup vs baseline: 1.2331x; 1.2331x over previous
#include <cuda_runtime.h>
#include <math.h>
#include <stdint.h>
#include <limits.h>

#define T_DIM   4096
#define V_DIM   4096
#define FW      5
#define B_DIM   64
#define S_DIM   512
#define NROWS   (B_DIM * S_DIM)      // 32768
#define NPAIRS  (T_DIM / 2)          // 2048
#define ROWBLKS (NROWS / 32)         // 1024
#define SLAB_ELEMS (V_DIM * FW)      // 20480 float2 entries

// Scratch logits: block layout [rowBlk][tpair][row-in-blk] as float2 (t=2c, 2c+1).
__device__ float2 g_scratch[(size_t)ROWBLKS * NPAIRS * 32];

// ---------------------------------------------------------------------------
__global__ void k0_zero(float* out) {
    if (threadIdx.x == 0) out[2 * NROWS] = 0.0f;
}

// ---------------------------------------------------------------------------
// K1: per t-pair CTA, 512 threads (thread = sequence position s). Stage
// W[t0,:,:], W[t1,:,:] into SMEM interleaved float2; gather-sum in the
// reference's exact fp32 add order (b + k0 + k1 + k2 + k3 + k4).
// ---------------------------------------------------------------------------
__global__ __launch_bounds__(512, 1)
void k1_logits(const float* __restrict__ W, const float* __restrict__ b,
               const int* __restrict__ x) {
    extern __shared__ float2 slab[];   // 20480 float2 = 160 KB

    const int c  = blockIdx.x;
    const int t0 = 2 * c;

    {
        const float4* w0 = (const float4*)(W + (size_t)t0 * SLAB_ELEMS);
        const float4* w1 = (const float4*)(W + (size_t)(t0 + 1) * SLAB_ELEMS);
        float4* slab4 = (float4*)slab;
        for (int i = threadIdx.x; i < SLAB_ELEMS / 4; i += 512) {
            float4 a = w0[i];
            float4 d = w1[i];
            slab4[2 * i + 0] = make_float4(a.x, d.x, a.y, d.y);
            slab4[2 * i + 1] = make_float4(a.z, d.z, a.w, d.w);
        }
    }
    const float2 bb = make_float2(__ldg(b + t0), __ldg(b + t0 + 1));
    __syncthreads();

    const int s = threadIdx.x;
    const bool interior = (s >= 2) && (s <= S_DIM - 3);
    const int lane = threadIdx.x & 31;
    const int wsub = threadIdx.x >> 5;

    for (int bi = 0; bi < B_DIM; bi++) {
        const int* xr = x + bi * S_DIM;
        float2 a = bb;
        if (interior) {
            int v0 = __ldg(xr + s - 2);
            int v1 = __ldg(xr + s - 1);
            int v2 = __ldg(xr + s);
            int v3 = __ldg(xr + s + 1);
            int v4 = __ldg(xr + s + 2);
            float2 w0 = slab[v0 * 5 + 0];
            float2 w1 = slab[v1 * 5 + 1];
            float2 w2 = slab[v2 * 5 + 2];
            float2 w3 = slab[v3 * 5 + 3];
            float2 w4 = slab[v4 * 5 + 4];
            a.x += w0.x; a.y += w0.y;
            a.x += w1.x; a.y += w1.y;
            a.x += w2.x; a.y += w2.y;
            a.x += w3.x; a.y += w3.y;
            a.x += w4.x; a.y += w4.y;
        } else {
            #pragma unroll
            for (int k = 0; k < FW; k++) {
                int j = s + k - 2;
                if (j >= 0 && j < S_DIM) {
                    float2 w = slab[xr[j] * 5 + k];
                    a.x += w.x; a.y += w.y;
                }
            }
        }
        size_t ridx = (((size_t)(bi * 16 + wsub)) * NPAIRS + c) * 32 + lane;
        g_scratch[ridx] = a;   // 256B coalesced per warp
    }
}

// ---------------------------------------------------------------------------
// K2: per row-block (32 rows) CTA of 1024 threads; grid split in halves.
// warp = c-stripe, lane = row. Pass 1: max + Kahan fp32 sum(e^l) (4 partials,
// 8-deep load batching) + fp32 sum(l e^l). Double precision only in the
// 32-way final reduction (few ops). Pass 2: tie-aware argmax replicating
// jnp.argmax(exp(log_softmax)) first-index semantics.
// ---------------------------------------------------------------------------
__global__ __launch_bounds__(1024)
void k2_softmax(float* __restrict__ out, int rbase) {
    __shared__ float  sm_m[32][33];
    __shared__ double sm_s[32][33];
    __shared__ float  sm_w[32][33];
    __shared__ float  row_m[32];
    __shared__ float  row_lse[32];
    __shared__ int    row_cand[32];

    const int rblk = rbase + blockIdx.x;
    const int warp = threadIdx.x >> 5;
    const int lane = threadIdx.x & 31;

    const float2* base = g_scratch + (size_t)rblk * NPAIRS * 32;

    // ---- pass 1: 4 accumulator sets, 8-deep load batches ----
    float m4[4], s4[4], c4[4], w4[4];
    #pragma unroll
    for (int a = 0; a < 4; a++) {
        m4[a] = -INFINITY; s4[a] = 0.0f; c4[a] = 0.0f; w4[a] = 0.0f;
    }

    for (int i = 0; i < NPAIRS / 32; i += 8) {
        float2 v[8];
        #pragma unroll
        for (int j = 0; j < 8; j++)
            v[j] = base[(size_t)((i + j) * 32 + warp) * 32 + lane];
        #pragma unroll
        for (int j = 0; j < 8; j++) {
            const int a = j & 3;
            m4[a] = fmaxf(m4[a], fmaxf(v[j].x, v[j].y));
            float ex = __expf(v[j].x);
            float ey = __expf(v[j].y);
            float e  = ex + ey;                 // same pair pre-add as before
            // Kahan accumulate e into (s4[a], c4[a])
            float y = e - c4[a];
            float t = s4[a] + y;
            c4[a] = (t - s4[a]) - y;
            s4[a] = t;
            w4[a] = fmaf(v[j].x, ex, w4[a]);
            w4[a] = fmaf(v[j].y, ey, w4[a]);
        }
    }
    float  m  = fmaxf(fmaxf(m4[0], m4[1]), fmaxf(m4[2], m4[3]));
    double sd = ((double)s4[0] + (double)c4[0]) + ((double)s4[1] + (double)c4[1])
              + ((double)s4[2] + (double)c4[2]) + ((double)s4[3] + (double)c4[3]);
    float  w  = (w4[0] + w4[1]) + (w4[2] + w4[3]);

    sm_m[warp][lane] = m;
    sm_s[warp][lane] = sd;
    sm_w[warp][lane] = w;
    __syncthreads();

    // ---- reduction: warp `warp` reduces row `warp` ----
    {
        float  m2 = sm_m[lane][warp];
        double s2 = sm_s[lane][warp];
        float  w2 = sm_w[lane][warp];
        #pragma unroll
        for (int off = 16; off > 0; off >>= 1) {
            m2 = fmaxf(m2, __shfl_down_sync(0xffffffffu, m2, off));
            s2 += __shfl_down_sync(0xffffffffu, s2, off);
            w2 += __shfl_down_sync(0xffffffffu, w2, off);
        }
        if (lane == 0) {
            double ls0 = log(s2);                       // ln(sum e^l), double
            float  lse_f = (float)(ls0 - (double)m2);   // ref's log(sum e^{l-m})
            row_m[warp]   = m2;
            row_lse[warp] = lse_f;
            row_cand[warp] = INT_MAX;
            int r = rblk * 32 + warp;
            out[NROWS + r] = -lse_f;                    // log_p at argmax (tie key)
            float H = (float)ls0 - (float)(s2 != 0.0 ? (double)w2 / s2 : 0.0);
            atomicAdd(out + 2 * NROWS,
                      H * (1.0f / ((float)NROWS * (float)T_DIM)));
        }
    }
    __syncthreads();

    // ---- pass 2: tie-aware argmax (rare rescan) ----
    {
        float mr   = row_m[lane];
        float lsef = row_lse[lane];
        float nlse = 0.0f - lsef;          // key of the max element
        if (m >= mr - 2e-6f) {             // this stripe may hold a candidate
            for (int i = 0; i < NPAIRS / 32; i++) {
                int c = i * 32 + warp;
                float2 v = base[(size_t)c * 32 + lane];
                float shx = v.x - mr;
                if (shx > -2e-6f) {
                    if ((shx - lsef) == nlse) atomicMin(&row_cand[lane], 2 * c);
                }
                float shy = v.y - mr;
                if (shy > -2e-6f) {
                    if ((shy - lsef) == nlse) atomicMin(&row_cand[lane], 2 * c + 1);
                }
            }
        }
    }
    __syncthreads();

    if (warp == 0) {
        out[rblk * 32 + lane] = (float)row_cand[lane];
    }
}

// ---------------------------------------------------------------------------
extern "C" void kernel_launch(void* const* d_in, const int* in_sizes, int n_in,
                              void* d_out, int out_size) {
    const float* W = nullptr;
    const float* b = nullptr;
    const int*   x = nullptr;
    for (int i = 0; i < n_in; i++) {
        if (in_sizes[i] == T_DIM * V_DIM * FW) W = (const float*)d_in[i];
        else if (in_sizes[i] == T_DIM)         b = (const float*)d_in[i];
        else if (in_sizes[i] == NROWS)         x = (const int*)d_in[i];
    }
    float* out = (float*)d_out;

    cudaFuncSetAttribute(k1_logits, cudaFuncAttributeMaxDynamicSharedMemorySize,
                         SLAB_ELEMS * (int)sizeof(float2));

    // 4 launches per call so ncu -s 5 -c 1 lands on k1 of the 2nd invocation.
    k0_zero<<<1, 32>>>(out);
    k1_logits<<<NPAIRS, 512, SLAB_ELEMS * sizeof(float2)>>>(W, b, x);
    k2_softmax<<<ROWBLKS / 2, 1024>>>(out, 0);
    k2_softmax<<<ROWBLKS / 2, 1024>>>(out, ROWBLKS / 2);
}